// round 13
// baseline (speedup 1.0000x reference)
#include <cuda_runtime.h>
#include <stdint.h>
#include <math.h>

#define TT 2048
#define BB 16
#define NN 2048
#define HH 1024
#define SPL 32
#define CHUNK 64    // timesteps per CTA before masking (~32 survive)
#define THR 256     // k_main threads (8 warps), 2 CTAs/SM

// scratch (device globals: no allocation allowed in kernel_launch)
__device__ float g_decfea[BB*NN];
__device__ float g_scores[TT*BB];     // only unmasked entries written
__device__ float g_m[BB*SPL];
__device__ float g_z[BB*SPL];
__device__ float g_acc[BB*SPL*NN];    // 4 MB
__device__ unsigned char g_mask8[TT*BB];

// single-MUFU tanh (sm_75+), abs err ~2e-4 — fine vs 1e-3 threshold
__device__ __forceinline__ float tanhfast(float x){
    float y;
    asm("tanh.approx.f32 %0, %1;" : "=f"(y) : "f"(x));
    return y;
}

__device__ __forceinline__ float4 ldcs4(const float4* p){
    float4 r;
    asm("ld.global.cs.v4.f32 {%0,%1,%2,%3}, [%4];"
        : "=f"(r.x), "=f"(r.y), "=f"(r.z), "=f"(r.w) : "l"(p));
    return r;
}

// ---------------------------------------------------------------------------
// Kernel 1: dec_fea[b,n] = dot(dec[b,:], Wd[n,:]) + bd[n].
// 128 CTAs x 128 thr (4 warps); each WARP owns 4 consecutive n-rows, so every
// dec smem read is reused 4x (LDS traffic 128 MB -> 32 MB chip-wide).
// Wd chunks double-buffered in regs. lane0 stores 4 outputs as one STG.128.
// Also converts the padding mask to uint8 (dtype auto-detected).
// ---------------------------------------------------------------------------
__global__ __launch_bounds__(128) void k_decfea(
    const float* __restrict__ dec,
    const float* __restrict__ Wd,
    const float* __restrict__ bd,
    const unsigned char* __restrict__ mraw){
    extern __shared__ float sdec[];    // 64 KB (dynamic: 16B-aligned)
    // ---- mask conversion: 16384 threads x 2 elements ----
    {
        const unsigned int* w = (const unsigned int*)mraw;
        int is_word = 1;   // int32 (0/1) or float32 (0.0/1.0) storage
        #pragma unroll
        for (int i = 0; i < 32; ++i){
            unsigned int x = w[i];
            if (x != 0u && x != 1u && x != 0x3F800000u) is_word = 0;
        }
        int idx = blockIdx.x*128 + threadIdx.x;
        #pragma unroll
        for (int h = 0; h < 2; ++h){
            int id2 = idx + h*16384;
            unsigned char mv = is_word ? (unsigned char)(w[id2] != 0u)
                                       : (unsigned char)(mraw[id2] != 0);
            g_mask8[id2] = mv;
        }
    }

    int tid  = threadIdx.x;
    int wid  = tid >> 5, lane = tid & 31;

    // stage all of dec: 4096 float4 / 128 thr = 32 each
    {
        const float4* dg = (const float4*)dec;
        float4* sg = (float4*)sdec;
        #pragma unroll
        for (int i = 0; i < 32; ++i) sg[tid + i*128] = dg[tid + i*128];
    }
    __syncthreads();

    int nbase = blockIdx.x*16 + wid*4;   // this warp's 4 rows
    const float4* wp0 = (const float4*)(Wd + (size_t)(nbase+0)*HH);
    const float4* wp1 = (const float4*)(Wd + (size_t)(nbase+1)*HH);
    const float4* wp2 = (const float4*)(Wd + (size_t)(nbase+2)*HH);
    const float4* wp3 = (const float4*)(Wd + (size_t)(nbase+3)*HH);
    const float4* sd  = (const float4*)sdec;

    float acc0[BB], acc1[BB], acc2[BB], acc3[BB];
    #pragma unroll
    for (int b = 0; b < BB; ++b){ acc0[b]=0.f; acc1[b]=0.f; acc2[b]=0.f; acc3[b]=0.f; }

    float4 wa = wp0[lane], wb = wp1[lane], wcx = wp2[lane], wdd = wp3[lane];
    #pragma unroll
    for (int ch = 0; ch < 8; ++ch){
        float4 na, nb2, nc, nd;
        if (ch < 7){
            na  = wp0[(ch+1)*32 + lane];
            nb2 = wp1[(ch+1)*32 + lane];
            nc  = wp2[(ch+1)*32 + lane];
            nd  = wp3[(ch+1)*32 + lane];
        }
        #pragma unroll
        for (int b = 0; b < BB; ++b){
            float4 d = sd[b*256 + ch*32 + lane];
            acc0[b] += wa.x*d.x  + wa.y*d.y  + wa.z*d.z  + wa.w*d.w;
            acc1[b] += wb.x*d.x  + wb.y*d.y  + wb.z*d.z  + wb.w*d.w;
            acc2[b] += wcx.x*d.x + wcx.y*d.y + wcx.z*d.z + wcx.w*d.w;
            acc3[b] += wdd.x*d.x + wdd.y*d.y + wdd.z*d.z + wdd.w*d.w;
        }
        if (ch < 7){ wa = na; wb = nb2; wcx = nc; wdd = nd; }
    }

    float4 bias = *(const float4*)(bd + nbase);
    #pragma unroll
    for (int b = 0; b < BB; ++b){
        float s0 = acc0[b], s1 = acc1[b], s2 = acc2[b], s3 = acc3[b];
        #pragma unroll
        for (int off = 16; off; off >>= 1){
            s0 += __shfl_xor_sync(0xffffffffu, s0, off);
            s1 += __shfl_xor_sync(0xffffffffu, s1, off);
            s2 += __shfl_xor_sync(0xffffffffu, s2, off);
            s3 += __shfl_xor_sync(0xffffffffu, s3, off);
        }
        if (lane == 0){
            float4 o = make_float4(s0 + bias.x, s1 + bias.y, s2 + bias.z, s3 + bias.w);
            *(float4*)(g_decfea + b*NN + nbase) = o;
        }
    }
}

// ---------------------------------------------------------------------------
// Kernel 2: fused scores + online softmax + context partial, mask-compacted,
// ONE barrier per iteration: lane0s publish warp partials to a double-
// buffered, 16B-ALIGNED sred[buf][score][warp]; after the barrier EVERY
// thread sums the 8 warp values itself (broadcast LDS.128, fixed order).
// grid (SPL, BB) = 512 CTAs; 256 thr; 2 CTAs/SM; 4-row register prefetch.
// ---------------------------------------------------------------------------
__global__ __launch_bounds__(THR, 2) void k_main(
    const float* __restrict__ enc,
    const float* __restrict__ cov,
    const float* __restrict__ wc,
    const float* __restrict__ v)
{
    __shared__ __align__(16) float sred[2][4][8];   // [buf][score][warp]
    __shared__ __align__(16) float scov[CHUNK];
    __shared__ short slist[CHUNK];    // compacted local t-indices (unmasked)
    __shared__ unsigned char smask[CHUNK];
    __shared__ int   scnt;
    int tid  = threadIdx.x;
    int wid  = tid >> 5, lane = tid & 31;
    int sp = blockIdx.x, b = blockIdx.y;
    int t0 = sp * CHUNK;

    if (tid < CHUNK){
        scov[tid]  = cov[(t0 + tid)*BB + b];
        smask[tid] = g_mask8[(t0 + tid)*BB + b];
    }
    int n0 = tid * 8;
    float4 df0 = *(const float4*)(g_decfea + b*NN + n0);
    float4 df1 = *(const float4*)(g_decfea + b*NN + n0 + 4);
    float4 w0  = *(const float4*)(wc + n0);
    float4 w1  = *(const float4*)(wc + n0 + 4);
    float4 v0  = *(const float4*)(v + n0);
    float4 v1  = *(const float4*)(v + n0 + 4);
    __syncthreads();

    // ---- build compacted unmasked list (warp 0, ballot + popc) ----
    if (tid < 32){
        unsigned mk0 = __ballot_sync(0xffffffffu, smask[tid] == 0);
        unsigned mk1 = __ballot_sync(0xffffffffu, smask[32 + tid] == 0);
        int c0 = __popc(mk0);
        int cnt = c0 + __popc(mk1);
        if (smask[tid] == 0)
            slist[__popc(mk0 & ((1u << tid) - 1u))] = (short)tid;
        if (smask[32 + tid] == 0)
            slist[c0 + __popc(mk1 & ((1u << tid) - 1u))] = (short)(32 + tid);
        __syncwarp();
        if (tid == 0){
            scnt = cnt;
            int padded = (cnt + 3) & ~3;
            for (int i = cnt; i < padded; ++i) slist[i] = slist[cnt > 0 ? cnt-1 : 0];
        }
    }
    __syncthreads();
    int cnt = scnt;

    float m = -INFINITY, Z = 0.f;
    float4 A0 = make_float4(0.f,0.f,0.f,0.f);
    float4 A1 = make_float4(0.f,0.f,0.f,0.f);

    if (cnt > 0){
        int nb = (cnt + 3) >> 2;
        // prefetch batch 0 (4 compacted rows)
        int li[4];
        float4 c0[4], c1[4];
        #pragma unroll
        for (int i = 0; i < 4; ++i){
            li[i] = slist[i];
            const float4* rp = (const float4*)(enc + ((size_t)(t0+li[i])*BB + b)*NN + n0);
            c0[i] = ldcs4(rp); c1[i] = ldcs4(rp + 1);
        }
        for (int it = 0; it < nb; ++it){
            int cur = it & 1;
            bool havenext = (it + 1 < nb);
            int ni[4];
            float4 x0[4], x1[4];
            if (havenext){
                #pragma unroll
                for (int i = 0; i < 4; ++i){
                    ni[i] = slist[(it+1)*4 + i];
                    const float4* rp = (const float4*)(enc + ((size_t)(t0+ni[i])*BB + b)*NN + n0);
                    x0[i] = ldcs4(rp); x1[i] = ldcs4(rp + 1);
                }
            }
            float part[4];
            #pragma unroll
            for (int i = 0; i < 4; ++i){
                float cv = scov[li[i]];
                float p;
                p  = tanhfast(fmaf(cv, w0.x, c0[i].x + df0.x)) * v0.x;
                p += tanhfast(fmaf(cv, w0.y, c0[i].y + df0.y)) * v0.y;
                p += tanhfast(fmaf(cv, w0.z, c0[i].z + df0.z)) * v0.z;
                p += tanhfast(fmaf(cv, w0.w, c0[i].w + df0.w)) * v0.w;
                p += tanhfast(fmaf(cv, w1.x, c1[i].x + df1.x)) * v1.x;
                p += tanhfast(fmaf(cv, w1.y, c1[i].y + df1.y)) * v1.y;
                p += tanhfast(fmaf(cv, w1.z, c1[i].z + df1.z)) * v1.z;
                p += tanhfast(fmaf(cv, w1.w, c1[i].w + df1.w)) * v1.w;
                part[i] = p;
            }
            // warp reduce 4 partials; lane0 publishes to sred[cur]
            #pragma unroll
            for (int i = 0; i < 4; ++i)
                #pragma unroll
                for (int off = 16; off; off >>= 1)
                    part[i] += __shfl_xor_sync(0xffffffffu, part[i], off);
            if (lane == 0){
                #pragma unroll
                for (int i = 0; i < 4; ++i) sred[cur][i][wid] = part[i];
            }
            __syncthreads();   // the ONLY barrier this iteration

            // every thread sums the 8 warp partials (broadcast LDS, fixed order)
            float s[4];
            #pragma unroll
            for (int i = 0; i < 4; ++i){
                float4 a = *(const float4*)&sred[cur][i][0];
                float4 e = *(const float4*)&sred[cur][i][4];
                s[i] = ((a.x + a.y) + (a.z + a.w)) + ((e.x + e.y) + (e.z + e.w));
            }
            // publish scores for valid entries
            #pragma unroll
            for (int i = 0; i < 4; ++i)
                if (tid == i && it*4 + i < cnt)
                    g_scores[(t0 + li[i])*BB + b] = s[i];
            #pragma unroll
            for (int i = 0; i < 4; ++i)
                if (it*4 + i >= cnt) s[i] = -INFINITY;

            // online softmax update (pads: p=0)
            float m2 = m;
            #pragma unroll
            for (int i = 0; i < 4; ++i) m2 = fmaxf(m2, s[i]);
            float sc = __expf(m - m2);             // m==-inf -> 0 (A still 0)
            float p[4];
            #pragma unroll
            for (int i = 0; i < 4; ++i) p[i] = __expf(s[i] - m2);
            Z = Z*sc + (p[0]+p[1]) + (p[2]+p[3]);
            float ax = A0.x*sc, ay = A0.y*sc, az = A0.z*sc, aw = A0.w*sc;
            float bx = A1.x*sc, by = A1.y*sc, bz = A1.z*sc, bw = A1.w*sc;
            #pragma unroll
            for (int i = 0; i < 4; ++i){
                ax = fmaf(p[i], c0[i].x, ax); ay = fmaf(p[i], c0[i].y, ay);
                az = fmaf(p[i], c0[i].z, az); aw = fmaf(p[i], c0[i].w, aw);
                bx = fmaf(p[i], c1[i].x, bx); by = fmaf(p[i], c1[i].y, by);
                bz = fmaf(p[i], c1[i].z, bz); bw = fmaf(p[i], c1[i].w, bw);
            }
            A0 = make_float4(ax, ay, az, aw);
            A1 = make_float4(bx, by, bz, bw);
            m = m2;

            if (havenext){
                #pragma unroll
                for (int i = 0; i < 4; ++i){
                    li[i] = ni[i]; c0[i] = x0[i]; c1[i] = x1[i];
                }
            }
        }
    }
    if (tid == 0){
        g_m[b*SPL + sp] = m;
        g_z[b*SPL + sp] = Z;
    }
    float4* op = (float4*)(g_acc + (size_t)(b*SPL + sp)*NN + n0);
    op[0] = A0; op[1] = A1;
}

// ---------------------------------------------------------------------------
// Kernel 3: combine. blocks 0..31: context c[b, n-half]. blocks 32..159:
// attn + coverage, float4 flat-indexed; masked entries -> attn 0.
// ---------------------------------------------------------------------------
__global__ void k_combine(const float* __restrict__ cov,
                          float* __restrict__ out){
    int tid = threadIdx.x;
    if (blockIdx.x < 2*BB){
        int b = blockIdx.x >> 1, h = blockIdx.x & 1;
        __shared__ __align__(16) float sw[SPL];
        if (tid < 32){
            float mv = g_m[b*SPL + tid];
            float zv = g_z[b*SPL + tid];
            float M = mv;
            #pragma unroll
            for (int off = 16; off; off >>= 1)
                M = fmaxf(M, __shfl_xor_sync(0xffffffffu, M, off));
            float Zs = zv * __expf(mv - M);
            #pragma unroll
            for (int off = 16; off; off >>= 1)
                Zs += __shfl_xor_sync(0xffffffffu, Zs, off);
            float inv = 1.0f / Zs;
            sw[tid] = __expf(mv - M) * inv;
        }
        __syncthreads();
        int n0 = h*1024 + tid*4;
        float4 r = make_float4(0.f,0.f,0.f,0.f);
        #pragma unroll
        for (int s = 0; s < SPL; ++s){
            float4 x = *(const float4*)(g_acc + (size_t)(b*SPL + s)*NN + n0);
            float wgt = sw[s];
            r.x = fmaf(wgt, x.x, r.x); r.y = fmaf(wgt, x.y, r.y);
            r.z = fmaf(wgt, x.z, r.z); r.w = fmaf(wgt, x.w, r.w);
        }
        *(float4*)(out + b*NN + n0) = r;
    } else {
        __shared__ float sM[BB], sInv[BB];
        if (tid < BB){
            int b = tid;
            float M = -INFINITY;
            #pragma unroll
            for (int s = 0; s < SPL; ++s) M = fmaxf(M, g_m[b*SPL + s]);
            float Zs = 0.f;
            #pragma unroll
            for (int s = 0; s < SPL; ++s) Zs += g_z[b*SPL + s] * __expf(g_m[b*SPL + s] - M);
            sM[b] = M; sInv[b] = 1.0f / Zs;
        }
        __syncthreads();
        int q = (blockIdx.x - 2*BB) * 256 + tid;    // 128 blocks -> 8192 quads
        int flat = q * 4;
        if (q < (TT*BB)/4){
            float4 sc = *(const float4*)(g_scores + flat);
            float4 cv = *(const float4*)(cov + flat);
            uchar4 mk = *(const uchar4*)(g_mask8 + flat);
            int b0 = flat & (BB-1);
            float4 a;
            a.x = mk.x ? 0.f : __expf(sc.x - sM[b0  ]) * sInv[b0  ];
            a.y = mk.y ? 0.f : __expf(sc.y - sM[b0+1]) * sInv[b0+1];
            a.z = mk.z ? 0.f : __expf(sc.z - sM[b0+2]) * sInv[b0+2];
            a.w = mk.w ? 0.f : __expf(sc.w - sM[b0+3]) * sInv[b0+3];
            *(float4*)(out + BB*NN + flat) = a;
            float4 cg = make_float4(cv.x + a.x, cv.y + a.y, cv.z + a.z, cv.w + a.w);
            *(float4*)(out + BB*NN + TT*BB + flat) = cg;
        }
    }
}

// ---------------------------------------------------------------------------
extern "C" void kernel_launch(void* const* d_in, const int* in_sizes, int n_in,
                              void* d_out, int out_size){
    const float*         dec  = (const float*)d_in[0];          // [B,H]
    const float*         enc  = (const float*)d_in[1];          // [T,B,N]
    const unsigned char* mask = (const unsigned char*)d_in[2];  // [T,B] (dtype auto-detected)
    const float*         cov  = (const float*)d_in[3];          // [T,B]
    const float*         Wd   = (const float*)d_in[4];          // [N,H]
    const float*         bd   = (const float*)d_in[5];          // [N]
    const float*         wc   = (const float*)d_in[6];          // [N]
    const float*         v    = (const float*)d_in[7];          // [N]
    float* out = (float*)d_out;  // c[B,N] | attn[T,B] | coverage_out[T,B]

    const int SMEM_DEC = BB*HH*4;                               // 64 KB
    cudaFuncSetAttribute(k_decfea, cudaFuncAttributeMaxDynamicSharedMemorySize, SMEM_DEC);

    k_decfea<<<128, 128, SMEM_DEC>>>(dec, Wd, bd, mask);
    k_main<<<dim3(SPL, BB), THR>>>(enc, cov, wc, v);
    k_combine<<<2*BB + (TT*BB/4 + 255)/256, 256>>>(cov, out);
}

// round 14
// speedup vs baseline: 1.0962x; 1.0962x over previous
#include <cuda_runtime.h>
#include <stdint.h>
#include <math.h>

#define TT 2048
#define BB 16
#define NN 2048
#define HH 1024
#define SPL 32
#define CHUNK 64    // timesteps per CTA before masking (~32 survive)
#define THR 256     // k_main threads (8 warps), 2 CTAs/SM

// scratch (device globals: no allocation allowed in kernel_launch)
__device__ float g_decfea[BB*NN];
__device__ float g_scores[TT*BB];     // only unmasked entries written
__device__ float g_m[BB*SPL];
__device__ float g_z[BB*SPL];
__device__ float g_acc[BB*SPL*NN];    // 4 MB
__device__ unsigned char g_mask8[TT*BB];

// single-MUFU tanh (sm_75+), abs err ~2e-4 — fine vs 1e-3 threshold
__device__ __forceinline__ float tanhfast(float x){
    float y;
    asm("tanh.approx.f32 %0, %1;" : "=f"(y) : "f"(x));
    return y;
}

__device__ __forceinline__ float4 ldcs4(const float4* p){
    float4 r;
    asm("ld.global.cs.v4.f32 {%0,%1,%2,%3}, [%4];"
        : "=f"(r.x), "=f"(r.y), "=f"(r.z), "=f"(r.w) : "l"(p));
    return r;
}

// ---------------------------------------------------------------------------
// Kernel 1: dec_fea[b,n] = dot(dec[b,:], Wd[n,:]) + bd[n].
// 256 CTAs x 128 thr (4 warps); each WARP owns 2 consecutive n-rows: dec smem
// reads reused 2x (LDS 128->64 MB chip-wide) while keeping 1024 warps
// (~7/SM) for latency hiding. Wd rows preloaded (MLP 16). lane0 stores the
// row pair as one float2. Also converts the padding mask to uint8.
// ---------------------------------------------------------------------------
__global__ __launch_bounds__(128) void k_decfea(
    const float* __restrict__ dec,
    const float* __restrict__ Wd,
    const float* __restrict__ bd,
    const unsigned char* __restrict__ mraw){
    extern __shared__ float sdec[];    // 64 KB (dynamic: 16B-aligned)
    // ---- mask conversion: 256*128 = 32768 threads, one element each ----
    {
        const unsigned int* w = (const unsigned int*)mraw;
        int is_word = 1;   // int32 (0/1) or float32 (0.0/1.0) storage
        #pragma unroll
        for (int i = 0; i < 32; ++i){
            unsigned int x = w[i];
            if (x != 0u && x != 1u && x != 0x3F800000u) is_word = 0;
        }
        int idx = blockIdx.x*128 + threadIdx.x;
        unsigned char mv = is_word ? (unsigned char)(w[idx] != 0u)
                                   : (unsigned char)(mraw[idx] != 0);
        g_mask8[idx] = mv;
    }

    int tid  = threadIdx.x;
    int wid  = tid >> 5, lane = tid & 31;

    int nbase = blockIdx.x*8 + wid*2;   // this warp's row pair
    const float4* wp0 = (const float4*)(Wd + (size_t)(nbase+0)*HH);
    const float4* wp1 = (const float4*)(Wd + (size_t)(nbase+1)*HH);

    // preload both Wd rows (16 independent LDG.128 in flight)
    float4 wv0[8], wv1[8];
    #pragma unroll
    for (int ch = 0; ch < 8; ++ch){
        wv0[ch] = wp0[ch*32 + lane];
        wv1[ch] = wp1[ch*32 + lane];
    }

    // stage all of dec: 4096 float4 / 128 thr = 32 each
    {
        const float4* dg = (const float4*)dec;
        float4* sg = (float4*)sdec;
        #pragma unroll
        for (int i = 0; i < 32; ++i) sg[tid + i*128] = dg[tid + i*128];
    }
    __syncthreads();

    const float4* sd = (const float4*)sdec;
    float acc0[BB], acc1[BB];
    #pragma unroll
    for (int b = 0; b < BB; ++b){ acc0[b] = 0.f; acc1[b] = 0.f; }

    #pragma unroll
    for (int ch = 0; ch < 8; ++ch){
        #pragma unroll
        for (int b = 0; b < BB; ++b){
            float4 d = sd[b*256 + ch*32 + lane];
            acc0[b] += wv0[ch].x*d.x + wv0[ch].y*d.y + wv0[ch].z*d.z + wv0[ch].w*d.w;
            acc1[b] += wv1[ch].x*d.x + wv1[ch].y*d.y + wv1[ch].z*d.z + wv1[ch].w*d.w;
        }
    }
    float bias0 = bd[nbase], bias1 = bd[nbase+1];
    #pragma unroll
    for (int b = 0; b < BB; ++b){
        float s0 = acc0[b], s1 = acc1[b];
        #pragma unroll
        for (int off = 16; off; off >>= 1){
            s0 += __shfl_xor_sync(0xffffffffu, s0, off);
            s1 += __shfl_xor_sync(0xffffffffu, s1, off);
        }
        if (lane == 0){
            float2 o = make_float2(s0 + bias0, s1 + bias1);
            *(float2*)(g_decfea + b*NN + nbase) = o;   // nbase even -> 8B aligned
        }
    }
}

// ---------------------------------------------------------------------------
// Kernel 2: fused scores + online softmax + context partial, mask-compacted
// (exact R11 body — proven fastest). grid (SPL, BB) = 512 CTAs; 256 thr;
// 2 CTAs/SM; 4-row register prefetch; two-stage reduction, two barriers.
// ---------------------------------------------------------------------------
__global__ __launch_bounds__(THR, 2) void k_main(
    const float* __restrict__ enc,
    const float* __restrict__ cov,
    const float* __restrict__ wc,
    const float* __restrict__ v)
{
    __shared__ float scov[CHUNK];
    __shared__ unsigned char smask[CHUNK];
    __shared__ short slist[CHUNK];    // compacted local t-indices (unmasked)
    __shared__ int   scnt;
    __shared__ float sred[8][5];      // [warp][score], padded
    __shared__ float sbc[4];
    int tid  = threadIdx.x;
    int wid  = tid >> 5, lane = tid & 31;
    int sp = blockIdx.x, b = blockIdx.y;
    int t0 = sp * CHUNK;

    if (tid < CHUNK){
        scov[tid]  = cov[(t0 + tid)*BB + b];
        smask[tid] = g_mask8[(t0 + tid)*BB + b];
    }
    int n0 = tid * 8;
    float4 df0 = *(const float4*)(g_decfea + b*NN + n0);
    float4 df1 = *(const float4*)(g_decfea + b*NN + n0 + 4);
    float4 w0  = *(const float4*)(wc + n0);
    float4 w1  = *(const float4*)(wc + n0 + 4);
    float4 v0  = *(const float4*)(v + n0);
    float4 v1  = *(const float4*)(v + n0 + 4);
    __syncthreads();

    // ---- build compacted unmasked list (warp 0, ballot + popc) ----
    if (tid < 32){
        unsigned mk0 = __ballot_sync(0xffffffffu, smask[tid] == 0);
        unsigned mk1 = __ballot_sync(0xffffffffu, smask[32 + tid] == 0);
        int c0 = __popc(mk0);
        int cnt = c0 + __popc(mk1);
        if (smask[tid] == 0)
            slist[__popc(mk0 & ((1u << tid) - 1u))] = (short)tid;
        if (smask[32 + tid] == 0)
            slist[c0 + __popc(mk1 & ((1u << tid) - 1u))] = (short)(32 + tid);
        __syncwarp();
        if (tid == 0){
            scnt = cnt;
            int padded = (cnt + 3) & ~3;
            for (int i = cnt; i < padded; ++i) slist[i] = slist[cnt > 0 ? cnt-1 : 0];
        }
    }
    __syncthreads();
    int cnt = scnt;

    float m = -INFINITY, Z = 0.f;
    float4 A0 = make_float4(0.f,0.f,0.f,0.f);
    float4 A1 = make_float4(0.f,0.f,0.f,0.f);

    if (cnt > 0){
        int nb = (cnt + 3) >> 2;
        // prefetch batch 0 (4 compacted rows)
        int li[4];
        float4 c0[4], c1[4];
        #pragma unroll
        for (int i = 0; i < 4; ++i){
            li[i] = slist[i];
            const float4* rp = (const float4*)(enc + ((size_t)(t0+li[i])*BB + b)*NN + n0);
            c0[i] = ldcs4(rp); c1[i] = ldcs4(rp + 1);
        }
        for (int it = 0; it < nb; ++it){
            bool havenext = (it + 1 < nb);
            int ni[4];
            float4 x0[4], x1[4];
            if (havenext){
                #pragma unroll
                for (int i = 0; i < 4; ++i){
                    ni[i] = slist[(it+1)*4 + i];
                    const float4* rp = (const float4*)(enc + ((size_t)(t0+ni[i])*BB + b)*NN + n0);
                    x0[i] = ldcs4(rp); x1[i] = ldcs4(rp + 1);
                }
            }
            float part[4];
            #pragma unroll
            for (int i = 0; i < 4; ++i){
                float cv = scov[li[i]];
                float p;
                p  = tanhfast(fmaf(cv, w0.x, c0[i].x + df0.x)) * v0.x;
                p += tanhfast(fmaf(cv, w0.y, c0[i].y + df0.y)) * v0.y;
                p += tanhfast(fmaf(cv, w0.z, c0[i].z + df0.z)) * v0.z;
                p += tanhfast(fmaf(cv, w0.w, c0[i].w + df0.w)) * v0.w;
                p += tanhfast(fmaf(cv, w1.x, c1[i].x + df1.x)) * v1.x;
                p += tanhfast(fmaf(cv, w1.y, c1[i].y + df1.y)) * v1.y;
                p += tanhfast(fmaf(cv, w1.z, c1[i].z + df1.z)) * v1.z;
                p += tanhfast(fmaf(cv, w1.w, c1[i].w + df1.w)) * v1.w;
                part[i] = p;
            }
            // stage 1: warp reduce 4 partials
            #pragma unroll
            for (int i = 0; i < 4; ++i)
                #pragma unroll
                for (int off = 16; off; off >>= 1)
                    part[i] += __shfl_xor_sync(0xffffffffu, part[i], off);
            if (lane == 0){
                #pragma unroll
                for (int i = 0; i < 4; ++i) sred[wid][i] = part[i];
            }
            __syncthreads();
            // stage 2: 32 threads, 8-lane groups, one score each
            if (tid < 32){
                int s  = tid >> 3;
                int ww = tid & 7;
                float val = sred[ww][s];
                val += __shfl_xor_sync(0xffffffffu, val, 1);
                val += __shfl_xor_sync(0xffffffffu, val, 2);
                val += __shfl_xor_sync(0xffffffffu, val, 4);
                if (ww == 0) sbc[s] = val;
            }
            __syncthreads();
            // scores for valid (non-pad) entries only
            if (tid < 4){
                int idx = it*4 + tid;
                if (idx < cnt) g_scores[(t0 + slist[idx])*BB + b] = sbc[tid];
            }
            float s[4];
            #pragma unroll
            for (int i = 0; i < 4; ++i)
                s[i] = (it*4 + i < cnt) ? sbc[i] : -INFINITY;

            // online softmax update (pads have s=-inf -> p=0, no contribution)
            float m2 = m;
            #pragma unroll
            for (int i = 0; i < 4; ++i) m2 = fmaxf(m2, s[i]);
            float sc = __expf(m - m2);             // m==-inf -> 0 (A still 0)
            float p[4];
            #pragma unroll
            for (int i = 0; i < 4; ++i) p[i] = __expf(s[i] - m2);
            Z = Z*sc + (p[0]+p[1]) + (p[2]+p[3]);
            float ax = A0.x*sc, ay = A0.y*sc, az = A0.z*sc, aw = A0.w*sc;
            float bx = A1.x*sc, by = A1.y*sc, bz = A1.z*sc, bw = A1.w*sc;
            #pragma unroll
            for (int i = 0; i < 4; ++i){
                ax = fmaf(p[i], c0[i].x, ax); ay = fmaf(p[i], c0[i].y, ay);
                az = fmaf(p[i], c0[i].z, az); aw = fmaf(p[i], c0[i].w, aw);
                bx = fmaf(p[i], c1[i].x, bx); by = fmaf(p[i], c1[i].y, by);
                bz = fmaf(p[i], c1[i].z, bz); bw = fmaf(p[i], c1[i].w, bw);
            }
            A0 = make_float4(ax, ay, az, aw);
            A1 = make_float4(bx, by, bz, bw);
            m = m2;

            if (havenext){
                #pragma unroll
                for (int i = 0; i < 4; ++i){
                    li[i] = ni[i]; c0[i] = x0[i]; c1[i] = x1[i];
                }
            }
        }
    }
    if (tid == 0){
        g_m[b*SPL + sp] = m;
        g_z[b*SPL + sp] = Z;
    }
    float4* op = (float4*)(g_acc + (size_t)(b*SPL + sp)*NN + n0);
    op[0] = A0; op[1] = A1;
}

// ---------------------------------------------------------------------------
// Kernel 3: combine. blocks 0..63: context c[b, n-quarter] (2x parallelism
// vs halves). blocks 64..191: attn + coverage, float4 flat-indexed; masked
// entries -> attn 0.
// ---------------------------------------------------------------------------
__global__ void k_combine(const float* __restrict__ cov,
                          float* __restrict__ out){
    int tid = threadIdx.x;
    if (blockIdx.x < 4*BB){
        int b = blockIdx.x >> 2, q = blockIdx.x & 3;
        __shared__ float sw[SPL];
        if (tid < 32){
            float mv = g_m[b*SPL + tid];
            float zv = g_z[b*SPL + tid];
            float M = mv;
            #pragma unroll
            for (int off = 16; off; off >>= 1)
                M = fmaxf(M, __shfl_xor_sync(0xffffffffu, M, off));
            float Zs = zv * __expf(mv - M);
            #pragma unroll
            for (int off = 16; off; off >>= 1)
                Zs += __shfl_xor_sync(0xffffffffu, Zs, off);
            float inv = 1.0f / Zs;
            sw[tid] = __expf(mv - M) * inv;
        }
        __syncthreads();
        if (tid < 128){
            int n0 = q*512 + tid*4;
            float4 r = make_float4(0.f,0.f,0.f,0.f);
            #pragma unroll
            for (int s = 0; s < SPL; ++s){
                float4 x = *(const float4*)(g_acc + (size_t)(b*SPL + s)*NN + n0);
                float wgt = sw[s];
                r.x = fmaf(wgt, x.x, r.x); r.y = fmaf(wgt, x.y, r.y);
                r.z = fmaf(wgt, x.z, r.z); r.w = fmaf(wgt, x.w, r.w);
            }
            *(float4*)(out + b*NN + n0) = r;
        }
    } else {
        __shared__ float sM[BB], sInv[BB];
        if (tid < BB){
            int b = tid;
            float M = -INFINITY;
            #pragma unroll
            for (int s = 0; s < SPL; ++s) M = fmaxf(M, g_m[b*SPL + s]);
            float Zs = 0.f;
            #pragma unroll
            for (int s = 0; s < SPL; ++s) Zs += g_z[b*SPL + s] * __expf(g_m[b*SPL + s] - M);
            sM[b] = M; sInv[b] = 1.0f / Zs;
        }
        __syncthreads();
        int q = (blockIdx.x - 4*BB) * 256 + tid;    // 128 blocks -> 8192 quads
        int flat = q * 4;
        if (q < (TT*BB)/4){
            float4 sc = *(const float4*)(g_scores + flat);
            float4 cv = *(const float4*)(cov + flat);
            uchar4 mk = *(const uchar4*)(g_mask8 + flat);
            int b0 = flat & (BB-1);
            float4 a;
            a.x = mk.x ? 0.f : __expf(sc.x - sM[b0  ]) * sInv[b0  ];
            a.y = mk.y ? 0.f : __expf(sc.y - sM[b0+1]) * sInv[b0+1];
            a.z = mk.z ? 0.f : __expf(sc.z - sM[b0+2]) * sInv[b0+2];
            a.w = mk.w ? 0.f : __expf(sc.w - sM[b0+3]) * sInv[b0+3];
            *(float4*)(out + BB*NN + flat) = a;
            float4 cg = make_float4(cv.x + a.x, cv.y + a.y, cv.z + a.z, cv.w + a.w);
            *(float4*)(out + BB*NN + TT*BB + flat) = cg;
        }
    }
}

// ---------------------------------------------------------------------------
extern "C" void kernel_launch(void* const* d_in, const int* in_sizes, int n_in,
                              void* d_out, int out_size){
    const float*         dec  = (const float*)d_in[0];          // [B,H]
    const float*         enc  = (const float*)d_in[1];          // [T,B,N]
    const unsigned char* mask = (const unsigned char*)d_in[2];  // [T,B] (dtype auto-detected)
    const float*         cov  = (const float*)d_in[3];          // [T,B]
    const float*         Wd   = (const float*)d_in[4];          // [N,H]
    const float*         bd   = (const float*)d_in[5];          // [N]
    const float*         wc   = (const float*)d_in[6];          // [N]
    const float*         v    = (const float*)d_in[7];          // [N]
    float* out = (float*)d_out;  // c[B,N] | attn[T,B] | coverage_out[T,B]

    const int SMEM_DEC = BB*HH*4;                               // 64 KB
    cudaFuncSetAttribute(k_decfea, cudaFuncAttributeMaxDynamicSharedMemorySize, SMEM_DEC);

    k_decfea<<<256, 128, SMEM_DEC>>>(dec, Wd, bd, mask);
    k_main<<<dim3(SPL, BB), THR>>>(enc, cov, wc, v);
    k_combine<<<4*BB + (TT*BB/4 + 255)/256, 256>>>(cov, out);
}